// round 16
// baseline (speedup 1.0000x reference)
#include <cuda_runtime.h>
#include <cuda_bf16.h>
#include <cuda_fp16.h>
#include <cstdint>

#define MAXN 100000
#define MAXE 1600000

// ---------------- device scratch ----------------
// INVARIANT: g_deg, g_cur, g_scan_ctr are ZERO at kernel_launch entry.
__device__ int      g_is64;
__device__ unsigned g_scan_ctr;
__device__ int      g_deg[MAXN];
__device__ int      g_off[MAXN + 1];
__device__ int      g_cur[MAXN];
__device__ int      g_bsum[128];
__device__ int      g_bucket[MAXE];
__device__ __half   g_x16[(size_t)MAXN * 128];   // fp16 copy of x
__device__ __half   g_agg16[(size_t)MAXN * 128]; // layer1 agg (fp16)
__device__ __half   g_h16[(size_t)MAXN * 256];   // hidden activations (fp16)
__device__ __half   g_t16[(size_t)MAXN * 64];    // layer2 t (fp16, aggregated)
__device__ float    g_u[(size_t)MAXN * 64];      // layer2 u (fp32)
__device__ unsigned g_w1p[128 * 256];            // [W1l;W1r] row-concat, k-pair packed
__device__ unsigned g_w2p[128 * 128];            // [W2l|W2r] col-concat, k-pair packed

__device__ __forceinline__ unsigned packh2(float a, float b) {
    __half2 h = __floats2half2_rn(a, b);
    return *reinterpret_cast<unsigned*>(&h);
}

__device__ __forceinline__ __half2 u2h(unsigned u) {
    return *reinterpret_cast<__half2*>(&u);
}

__device__ __forceinline__ int off_final(int i) {
    return g_off[i] + g_bsum[i >> 10];
}

// ---------------- cp.async helpers ----------------
__device__ __forceinline__ void cp16(void* smem_dst, const void* gsrc, int srcbytes) {
    unsigned saddr = (unsigned)__cvta_generic_to_shared(smem_dst);
    asm volatile("cp.async.cg.shared.global [%0], [%1], 16, %2;"
                 :: "r"(saddr), "l"(gsrc), "r"(srcbytes));
}
#define CP_COMMIT() asm volatile("cp.async.commit_group;")
#define CP_WAIT0()  asm volatile("cp.async.wait_group 0;")
#define CP_WAIT1()  asm volatile("cp.async.wait_group 1;")

// ---------------- prep: x->fp16 | weight pack | dtype detect | edge count ----------------
__global__ void prep_kernel(const float* __restrict__ x,
                            const float* __restrict__ W1l, const float* __restrict__ W1r,
                            const float* __restrict__ W2l, const float* __restrict__ W2r,
                            const void* __restrict__ ei,
                            int N, int E, int convBlocks, int packBlocks) {
    int bx = blockIdx.x;
    if (bx < convBlocks) {
        int i = bx * 256 + threadIdx.x;
        int total4 = N * 32;
        if (i < total4) {
            float4 v = ((const float4*)x)[i];
            uint2 o;
            o.x = packh2(v.x, v.y);
            o.y = packh2(v.z, v.w);
            *(uint2*)&g_x16[(size_t)i * 4] = o;
        }
    } else if (bx < convBlocks + packBlocks) {
        int w = (bx - convBlocks) * 256 + threadIdx.x;
        if (w < 128 * 256) {
            int k2 = w >> 8, n = w & 255;
            int r0 = 2 * k2;
            float a, b;
            if (r0 < 128) {
                a = W1l[(size_t)r0 * 256 + n];
                b = W1l[(size_t)(r0 + 1) * 256 + n];
            } else {
                a = W1r[(size_t)(r0 - 128) * 256 + n];
                b = W1r[(size_t)(r0 - 127) * 256 + n];
            }
            g_w1p[w] = packh2(a, b);
        } else {
            int w2 = w - 128 * 256;
            if (w2 < 128 * 128) {
                int k2 = w2 >> 7, n = w2 & 127;
                int r0 = 2 * k2;
                float a, b;
                if (n < 64) {
                    a = W2l[(size_t)r0 * 64 + n];
                    b = W2l[(size_t)(r0 + 1) * 64 + n];
                } else {
                    a = W2r[(size_t)r0 * 64 + (n - 64)];
                    b = W2r[(size_t)(r0 + 1) * 64 + (n - 64)];
                }
                g_w2p[w2] = packh2(a, b);
            }
        }
    } else if (bx == convBlocks + packBlocks) {
        if (threadIdx.x < 32) {
            const int* eiw = (const int*)ei;
            int nz = (eiw[2 * threadIdx.x + 1] != 0);
            unsigned any = __ballot_sync(0xffffffffu, nz);
            if (threadIdx.x == 0) g_is64 = (any == 0) ? 1 : 0;
        }
    } else {
        __shared__ int s64;
        const int* eiw = (const int*)ei;
        if (threadIdx.x < 32) {
            int nz = (eiw[2 * threadIdx.x + 1] != 0);
            unsigned any = __ballot_sync(0xffffffffu, nz);
            if (threadIdx.x == 0) s64 = (any == 0) ? 1 : 0;
        }
        __syncthreads();
        int is64 = s64;
        int eb = bx - (convBlocks + packBlocks + 1);
        int base = (eb * 256 + threadIdx.x) * 4;
        if (base >= E) return;
        int d[4];
        bool full = (base + 3 < E);
        if (is64) {
            const long long* p = (const long long*)ei + E + base;
            if (full) {
                longlong2 a = *(const longlong2*)p;
                longlong2 b = *(const longlong2*)(p + 2);
                d[0] = (int)a.x; d[1] = (int)a.y; d[2] = (int)b.x; d[3] = (int)b.y;
            } else {
                #pragma unroll
                for (int j = 0; j < 4; j++) d[j] = (base + j < E) ? (int)p[j] : -1;
            }
        } else {
            const int* p = (const int*)ei + E + base;
            if (full) {
                int4 v = *(const int4*)p;
                d[0] = v.x; d[1] = v.y; d[2] = v.z; d[3] = v.w;
            } else {
                #pragma unroll
                for (int j = 0; j < 4; j++) d[j] = (base + j < E) ? p[j] : -1;
            }
        }
        #pragma unroll
        for (int j = 0; j < 4; j++)
            if ((unsigned)d[j] < (unsigned)N) atomicAdd(&g_deg[d[j]], 1);
    }
}

// ---------------- scan ----------------
__global__ void scan_blocks(int N, int B) {
    __shared__ int wsum[32];
    __shared__ int isLast;
    int i = blockIdx.x * 1024 + threadIdx.x;
    int lane = threadIdx.x & 31, wid = threadIdx.x >> 5;
    int v = (i < N) ? g_deg[i] : 0;
    int s = v;
    #pragma unroll
    for (int o = 1; o < 32; o <<= 1) {
        int t = __shfl_up_sync(0xffffffffu, s, o);
        if (lane >= o) s += t;
    }
    if (lane == 31) wsum[wid] = s;
    __syncthreads();
    if (wid == 0) {
        int ws = wsum[lane];
        #pragma unroll
        for (int o = 1; o < 32; o <<= 1) {
            int t = __shfl_up_sync(0xffffffffu, ws, o);
            if (lane >= o) ws += t;
        }
        wsum[lane] = ws;
    }
    __syncthreads();
    int incl = s + (wid > 0 ? wsum[wid - 1] : 0);
    if (i < N) {
        g_off[i] = incl - v;
        g_deg[i] = 0;
        g_cur[i] = 0;
    }
    if (threadIdx.x == 1023) g_bsum[blockIdx.x] = incl;
    __threadfence();
    __syncthreads();
    if (threadIdx.x == 0) {
        unsigned old = atomicAdd(&g_scan_ctr, 1);
        isLast = (old == (unsigned)(gridDim.x - 1)) ? 1 : 0;
    }
    __syncthreads();
    if (isLast) {
        if (threadIdx.x == 0) g_scan_ctr = 0;
        if (threadIdx.x < 32) {
            int carry = 0;
            for (int base = 0; base < B; base += 32) {
                int idx = base + lane;
                int v2 = (idx < B) ? g_bsum[idx] : 0;
                int s2 = v2;
                #pragma unroll
                for (int o = 1; o < 32; o <<= 1) {
                    int t = __shfl_up_sync(0xffffffffu, s2, o);
                    if (lane >= o) s2 += t;
                }
                if (idx < B) g_bsum[idx] = carry + s2 - v2;
                carry += __shfl_sync(0xffffffffu, s2, 31);
            }
        }
    }
}

// ---------------- fill (4 edges/thread) ----------------
__global__ void fill_kernel(const void* __restrict__ ei, int E, int N) {
    int base = (blockIdx.x * blockDim.x + threadIdx.x) * 4;
    if (base >= E) return;
    int s[4], d[4];
    bool full = (base + 3 < E);
    if (g_is64) {
        const long long* ps = (const long long*)ei + base;
        const long long* pd = (const long long*)ei + E + base;
        if (full) {
            longlong2 a = *(const longlong2*)ps, b = *(const longlong2*)(ps + 2);
            longlong2 c = *(const longlong2*)pd, e = *(const longlong2*)(pd + 2);
            s[0] = (int)a.x; s[1] = (int)a.y; s[2] = (int)b.x; s[3] = (int)b.y;
            d[0] = (int)c.x; d[1] = (int)c.y; d[2] = (int)e.x; d[3] = (int)e.y;
        } else {
            #pragma unroll
            for (int j = 0; j < 4; j++) {
                s[j] = (base + j < E) ? (int)ps[j] : -1;
                d[j] = (base + j < E) ? (int)pd[j] : -1;
            }
        }
    } else {
        const int* ps = (const int*)ei + base;
        const int* pd = (const int*)ei + E + base;
        if (full) {
            int4 a = *(const int4*)ps;
            int4 c = *(const int4*)pd;
            s[0] = a.x; s[1] = a.y; s[2] = a.z; s[3] = a.w;
            d[0] = c.x; d[1] = c.y; d[2] = c.z; d[3] = c.w;
        } else {
            #pragma unroll
            for (int j = 0; j < 4; j++) {
                s[j] = (base + j < E) ? ps[j] : -1;
                d[j] = (base + j < E) ? pd[j] : -1;
            }
        }
    }
    #pragma unroll
    for (int j = 0; j < 4; j++) {
        if ((unsigned)d[j] < (unsigned)N && (unsigned)s[j] < (unsigned)N) {
            int pos = off_final(d[j]) + atomicAdd(&g_cur[d[j]], 1);
            g_bucket[pos] = s[j];
        }
    }
}

// ---------------- layer-1 mean aggregation: 16 lanes/node, uint4, 8-edge MLP ----------------
__global__ void agg128_kernel(int N, int E) {
    int lane = threadIdx.x & 15;                  // 16 lanes per node
    int node = blockIdx.x * 8 + (threadIdx.x >> 4);
    if (node >= N) return;
    int beg = off_final(node);
    int end = (node == N - 1) ? E : off_final(node + 1);
    unsigned lo = (unsigned)lane * 8;
    float acc[8];
    #pragma unroll
    for (int i = 0; i < 8; i++) acc[i] = 0.f;

    int e = beg;
    for (; e + 8 <= end; e += 8) {
        uint4 w[8];
        #pragma unroll
        for (int j = 0; j < 8; j++) {
            int sj = g_bucket[e + j];
            w[j] = *(const uint4*)&g_x16[(size_t)((unsigned)sj * 128u + lo)];
        }
        // fp16 tree over 8 edges per component
        #pragma unroll
        for (int c = 0; c < 4; c++) {
            unsigned* wc = &w[0].x;   // component c of w[j] is at ((unsigned*)&w[j])[c]
            __half2 t0 = __hadd2(u2h(((unsigned*)&w[0])[c]), u2h(((unsigned*)&w[1])[c]));
            __half2 t1 = __hadd2(u2h(((unsigned*)&w[2])[c]), u2h(((unsigned*)&w[3])[c]));
            __half2 t2 = __hadd2(u2h(((unsigned*)&w[4])[c]), u2h(((unsigned*)&w[5])[c]));
            __half2 t3 = __hadd2(u2h(((unsigned*)&w[6])[c]), u2h(((unsigned*)&w[7])[c]));
            __half2 tt = __hadd2(__hadd2(t0, t1), __hadd2(t2, t3));
            float2 f = __half22float2(tt);
            acc[c * 2] += f.x; acc[c * 2 + 1] += f.y;
            (void)wc;
        }
    }
    for (; e + 4 <= end; e += 4) {
        int s0 = g_bucket[e], s1 = g_bucket[e + 1], s2 = g_bucket[e + 2], s3 = g_bucket[e + 3];
        uint4 w0 = *(const uint4*)&g_x16[(size_t)((unsigned)s0 * 128u + lo)];
        uint4 w1 = *(const uint4*)&g_x16[(size_t)((unsigned)s1 * 128u + lo)];
        uint4 w2 = *(const uint4*)&g_x16[(size_t)((unsigned)s2 * 128u + lo)];
        uint4 w3 = *(const uint4*)&g_x16[(size_t)((unsigned)s3 * 128u + lo)];
        __half2 c0 = __hadd2(__hadd2(u2h(w0.x), u2h(w1.x)), __hadd2(u2h(w2.x), u2h(w3.x)));
        __half2 c1 = __hadd2(__hadd2(u2h(w0.y), u2h(w1.y)), __hadd2(u2h(w2.y), u2h(w3.y)));
        __half2 c2 = __hadd2(__hadd2(u2h(w0.z), u2h(w1.z)), __hadd2(u2h(w2.z), u2h(w3.z)));
        __half2 c3 = __hadd2(__hadd2(u2h(w0.w), u2h(w1.w)), __hadd2(u2h(w2.w), u2h(w3.w)));
        float2 f0 = __half22float2(c0), f1 = __half22float2(c1);
        float2 f2 = __half22float2(c2), f3 = __half22float2(c3);
        acc[0] += f0.x; acc[1] += f0.y; acc[2] += f1.x; acc[3] += f1.y;
        acc[4] += f2.x; acc[5] += f2.y; acc[6] += f3.x; acc[7] += f3.y;
    }
    for (; e < end; ++e) {
        int s = g_bucket[e];
        uint4 w = *(const uint4*)&g_x16[(size_t)((unsigned)s * 128u + lo)];
        float2 f0 = __half22float2(u2h(w.x)), f1 = __half22float2(u2h(w.y));
        float2 f2 = __half22float2(u2h(w.z)), f3 = __half22float2(u2h(w.w));
        acc[0] += f0.x; acc[1] += f0.y; acc[2] += f1.x; acc[3] += f1.y;
        acc[4] += f2.x; acc[5] += f2.y; acc[6] += f3.x; acc[7] += f3.y;
    }
    float inv = (end > beg) ? 1.f / (float)(end - beg) : 0.f;
    uint4 o;
    o.x = packh2(acc[0] * inv, acc[1] * inv);
    o.y = packh2(acc[2] * inv, acc[3] * inv);
    o.z = packh2(acc[4] * inv, acc[5] * inv);
    o.w = packh2(acc[6] * inv, acc[7] * inv);
    *(uint4*)&g_agg16[(size_t)((unsigned)node * 128u + lo)] = o;
}

// ---------------- fp16 MMA GEMMs (m16n8k16), 3-stage cp.async pipeline ----------------
#define MMA_H16(d, a, b)                                                        \
    asm volatile(                                                               \
        "mma.sync.aligned.m16n8k16.row.col.f32.f16.f16.f32 "                    \
        "{%0,%1,%2,%3}, {%4,%5,%6,%7}, {%8,%9}, {%0,%1,%2,%3};"                 \
        : "+f"(d[0]), "+f"(d[1]), "+f"(d[2]), "+f"(d[3])                        \
        : "r"(a[0]), "r"(a[1]), "r"(a[2]), "r"(a[3]), "r"(b[0]), "r"(b[1]))

template <int MODE>
__global__ void __launch_bounds__(256, 2)
gemm_h16(const float* __restrict__ bias, int M) {
    __shared__ unsigned As[3][128][20];
    __shared__ unsigned Ws[3][16][136];

    const int NI = 8;
    const int WSTRIDE = (MODE == 0) ? 256 : 128;
    const unsigned* __restrict__ Wp = (MODE == 0) ? g_w1p : g_w2p;

    int tid = threadIdx.x;
    int lane = tid & 31;
    int wid = tid >> 5;
    int warp_m = wid & 1;
    int warp_n = wid >> 1;
    int qk = lane & 3;
    int qr = lane >> 2;
    int row0 = blockIdx.y * 128;
    int col0 = blockIdx.x * 128;

    int am = tid >> 2;
    int aq = tid & 3;
    int wk = tid >> 5;
    int wn = (tid & 31) * 4;

    float d[4][4][4];
    #pragma unroll
    for (int i = 0; i < 4; i++)
        #pragma unroll
        for (int j = 0; j < 4; j++)
            #pragma unroll
            for (int q = 0; q < 4; q++) d[i][j][q] = 0.f;

    auto issue = [&](int it) {
        int st = it % 3;
        int k0 = it * 32;
        #pragma unroll
        for (int j = 0; j < 2; j++) {
            int grow = row0 + am + j * 64;
            int gr = (grow < M) ? grow : 0;
            int sz = (grow < M) ? 16 : 0;
            const void* src;
            if (MODE == 0) {
                const __half* sp = (k0 < 128) ? g_agg16 : g_x16;
                src = &sp[(size_t)gr * 128 + (k0 & 127) + aq * 8];
            } else {
                src = &g_h16[(size_t)gr * 256 + k0 + aq * 8];
            }
            cp16(&As[st][am + j * 64][aq * 4], src, sz);
        }
        #pragma unroll
        for (int j = 0; j < 2; j++) {
            int k2 = it * 16 + wk + j * 8;
            cp16(&Ws[st][wk + j * 8][wn], &Wp[(size_t)k2 * WSTRIDE + col0 + wn], 16);
        }
        CP_COMMIT();
    };

    issue(0);
    issue(1);
    for (int it = 0; it < NI; ++it) {
        if (it + 1 < NI) CP_WAIT1(); else CP_WAIT0();
        __syncthreads();
        if (it + 2 < NI) issue(it + 2);
        int st = it % 3;

        #pragma unroll
        for (int kk = 0; kk < 2; kk++) {
            int k2b = kk * 8;
            unsigned a[4][4], b[4][2];
            #pragma unroll
            for (int mf = 0; mf < 4; mf++) {
                int mrow = warp_m * 64 + mf * 16 + qr;
                a[mf][0] = As[st][mrow][k2b + qk];
                a[mf][1] = As[st][mrow + 8][k2b + qk];
                a[mf][2] = As[st][mrow][k2b + qk + 4];
                a[mf][3] = As[st][mrow + 8][k2b + qk + 4];
            }
            #pragma unroll
            for (int nf = 0; nf < 4; nf++) {
                int ncol = warp_n * 32 + nf * 8 + qr;
                b[nf][0] = Ws[st][k2b + qk][ncol];
                b[nf][1] = Ws[st][k2b + qk + 4][ncol];
            }
            #pragma unroll
            for (int mf = 0; mf < 4; mf++)
                #pragma unroll
                for (int nf = 0; nf < 4; nf++)
                    MMA_H16(d[mf][nf], a[mf], b[nf]);
        }
        __syncthreads();
    }

    #pragma unroll
    for (int nf = 0; nf < 4; nf++) {
        int col = col0 + warp_n * 32 + nf * 8 + qk * 2;
        if (MODE == 0) {
            float2 bv = *(const float2*)&bias[col];
            #pragma unroll
            for (int mf = 0; mf < 4; mf++) {
                int r0 = row0 + warp_m * 64 + mf * 16 + qr;
                if (r0 < M) {
                    unsigned hh = packh2(fmaxf(d[mf][nf][0] + bv.x, 0.f),
                                         fmaxf(d[mf][nf][1] + bv.y, 0.f));
                    *(unsigned*)&g_h16[(size_t)r0 * 256 + col] = hh;
                }
                if (r0 + 8 < M) {
                    unsigned hh = packh2(fmaxf(d[mf][nf][2] + bv.x, 0.f),
                                         fmaxf(d[mf][nf][3] + bv.y, 0.f));
                    *(unsigned*)&g_h16[(size_t)(r0 + 8) * 256 + col] = hh;
                }
            }
        } else {
            #pragma unroll
            for (int mf = 0; mf < 4; mf++) {
                int r0 = row0 + warp_m * 64 + mf * 16 + qr;
                if (col < 64) {
                    if (r0 < M) {
                        unsigned hh = packh2(d[mf][nf][0], d[mf][nf][1]);
                        *(unsigned*)&g_t16[(size_t)r0 * 64 + col] = hh;
                    }
                    if (r0 + 8 < M) {
                        unsigned hh = packh2(d[mf][nf][2], d[mf][nf][3]);
                        *(unsigned*)&g_t16[(size_t)(r0 + 8) * 64 + col] = hh;
                    }
                } else {
                    if (r0 < M) {
                        float2 o = make_float2(d[mf][nf][0], d[mf][nf][1]);
                        *(float2*)&g_u[(size_t)r0 * 64 + (col - 64)] = o;
                    }
                    if (r0 + 8 < M) {
                        float2 o = make_float2(d[mf][nf][2], d[mf][nf][3]);
                        *(float2*)&g_u[(size_t)(r0 + 8) * 64 + (col - 64)] = o;
                    }
                }
            }
        }
    }
}

// ---------------- final: 8 lanes/node, uint4, 8-edge MLP; out = sigmoid(mean(t)+u+b2) ----------------
__global__ void agg_sig_kernel(const float* __restrict__ b2, float* __restrict__ out,
                               int N, int E) {
    int lane = threadIdx.x & 7;                   // 8 lanes per node
    int node = blockIdx.x * 16 + (threadIdx.x >> 3);
    if (node >= N) return;
    int beg = off_final(node);
    int end = (node == N - 1) ? E : off_final(node + 1);
    unsigned lo = (unsigned)lane * 8;
    float acc[8];
    #pragma unroll
    for (int i = 0; i < 8; i++) acc[i] = 0.f;

    int e = beg;
    for (; e + 8 <= end; e += 8) {
        uint4 w[8];
        #pragma unroll
        for (int j = 0; j < 8; j++) {
            int sj = g_bucket[e + j];
            w[j] = *(const uint4*)&g_t16[(size_t)((unsigned)sj * 64u + lo)];
        }
        #pragma unroll
        for (int c = 0; c < 4; c++) {
            __half2 t0 = __hadd2(u2h(((unsigned*)&w[0])[c]), u2h(((unsigned*)&w[1])[c]));
            __half2 t1 = __hadd2(u2h(((unsigned*)&w[2])[c]), u2h(((unsigned*)&w[3])[c]));
            __half2 t2 = __hadd2(u2h(((unsigned*)&w[4])[c]), u2h(((unsigned*)&w[5])[c]));
            __half2 t3 = __hadd2(u2h(((unsigned*)&w[6])[c]), u2h(((unsigned*)&w[7])[c]));
            __half2 tt = __hadd2(__hadd2(t0, t1), __hadd2(t2, t3));
            float2 f = __half22float2(tt);
            acc[c * 2] += f.x; acc[c * 2 + 1] += f.y;
        }
    }
    for (; e + 4 <= end; e += 4) {
        int s0 = g_bucket[e], s1 = g_bucket[e + 1], s2 = g_bucket[e + 2], s3 = g_bucket[e + 3];
        uint4 w0 = *(const uint4*)&g_t16[(size_t)((unsigned)s0 * 64u + lo)];
        uint4 w1 = *(const uint4*)&g_t16[(size_t)((unsigned)s1 * 64u + lo)];
        uint4 w2 = *(const uint4*)&g_t16[(size_t)((unsigned)s2 * 64u + lo)];
        uint4 w3 = *(const uint4*)&g_t16[(size_t)((unsigned)s3 * 64u + lo)];
        __half2 c0 = __hadd2(__hadd2(u2h(w0.x), u2h(w1.x)), __hadd2(u2h(w2.x), u2h(w3.x)));
        __half2 c1 = __hadd2(__hadd2(u2h(w0.y), u2h(w1.y)), __hadd2(u2h(w2.y), u2h(w3.y)));
        __half2 c2 = __hadd2(__hadd2(u2h(w0.z), u2h(w1.z)), __hadd2(u2h(w2.z), u2h(w3.z)));
        __half2 c3 = __hadd2(__hadd2(u2h(w0.w), u2h(w1.w)), __hadd2(u2h(w2.w), u2h(w3.w)));
        float2 f0 = __half22float2(c0), f1 = __half22float2(c1);
        float2 f2 = __half22float2(c2), f3 = __half22float2(c3);
        acc[0] += f0.x; acc[1] += f0.y; acc[2] += f1.x; acc[3] += f1.y;
        acc[4] += f2.x; acc[5] += f2.y; acc[6] += f3.x; acc[7] += f3.y;
    }
    for (; e < end; ++e) {
        int s = g_bucket[e];
        uint4 w = *(const uint4*)&g_t16[(size_t)((unsigned)s * 64u + lo)];
        float2 f0 = __half22float2(u2h(w.x)), f1 = __half22float2(u2h(w.y));
        float2 f2 = __half22float2(u2h(w.z)), f3 = __half22float2(u2h(w.w));
        acc[0] += f0.x; acc[1] += f0.y; acc[2] += f1.x; acc[3] += f1.y;
        acc[4] += f2.x; acc[5] += f2.y; acc[6] += f3.x; acc[7] += f3.y;
    }
    float inv = (end > beg) ? 1.f / (float)(end - beg) : 0.f;
    float4 u0 = *(const float4*)&g_u[(size_t)((unsigned)node * 64u + lo)];
    float4 u1 = *(const float4*)&g_u[(size_t)((unsigned)node * 64u + lo + 4)];
    float4 b0 = *(const float4*)&b2[lo];
    float4 b1 = *(const float4*)&b2[lo + 4];
    float4 o0, o1;
    o0.x = 1.f / (1.f + __expf(-(acc[0] * inv + u0.x + b0.x)));
    o0.y = 1.f / (1.f + __expf(-(acc[1] * inv + u0.y + b0.y)));
    o0.z = 1.f / (1.f + __expf(-(acc[2] * inv + u0.z + b0.z)));
    o0.w = 1.f / (1.f + __expf(-(acc[3] * inv + u0.w + b0.w)));
    o1.x = 1.f / (1.f + __expf(-(acc[4] * inv + u1.x + b1.x)));
    o1.y = 1.f / (1.f + __expf(-(acc[5] * inv + u1.y + b1.y)));
    o1.z = 1.f / (1.f + __expf(-(acc[6] * inv + u1.z + b1.z)));
    o1.w = 1.f / (1.f + __expf(-(acc[7] * inv + u1.w + b1.w)));
    float* op = &out[(size_t)((unsigned)node * 64u + lo)];
    *(float4*)op = o0;
    *(float4*)(op + 4) = o1;
}

// ---------------- launch ----------------
extern "C" void kernel_launch(void* const* d_in, const int* in_sizes, int n_in,
                              void* d_out, int out_size) {
    const float* x   = (const float*)d_in[0];
    const void*  ei  = d_in[1];
    const float* W1l = (const float*)d_in[2];
    const float* W1r = (const float*)d_in[3];
    const float* b1  = (const float*)d_in[4];
    const float* W2l = (const float*)d_in[5];
    const float* W2r = (const float*)d_in[6];
    const float* b2  = (const float*)d_in[7];
    float* out = (float*)d_out;

    int N = in_sizes[0] / 128;
    int E = in_sizes[1] / 2;
    int B = (N + 1023) / 1024;

    int convBlocks = (N * 32 + 255) / 256;
    int packBlocks = (128 * 256 + 128 * 128 + 255) / 256;
    int E4blocks = ((E + 3) / 4 + 255) / 256;

    prep_kernel<<<convBlocks + packBlocks + 1 + E4blocks, 256>>>(
        x, W1l, W1r, W2l, W2r, ei, N, E, convBlocks, packBlocks);
    scan_blocks<<<B, 1024>>>(N, B);
    fill_kernel<<<E4blocks, 256>>>(ei, E, N);
    agg128_kernel<<<(N + 7) / 8, 128>>>(N, E);
    {
        dim3 grid(2, (N + 127) / 128);
        gemm_h16<0><<<grid, 256>>>(b1, N);
    }
    {
        dim3 grid(1, (N + 127) / 128);
        gemm_h16<1><<<grid, 256>>>(nullptr, N);
    }
    agg_sig_kernel<<<(N + 15) / 16, 128>>>(b2, out, N, E);
}

// round 17
// speedup vs baseline: 1.0313x; 1.0313x over previous
#include <cuda_runtime.h>
#include <cuda_bf16.h>
#include <cuda_fp16.h>
#include <cstdint>

#define MAXN 100000
#define MAXE 1600000

// ---------------- device scratch ----------------
// INVARIANT: g_deg, g_cur, g_scan_ctr are ZERO at kernel_launch entry.
__device__ int      g_is64;
__device__ unsigned g_scan_ctr;
__device__ int      g_deg[MAXN];
__device__ int      g_off[MAXN + 1];
__device__ int      g_cur[MAXN];
__device__ int      g_bsum[128];
__device__ int      g_bucket[MAXE];
__device__ __half   g_x16[(size_t)MAXN * 128];   // fp16 copy of x
__device__ __half   g_agg16[(size_t)MAXN * 128]; // layer1 agg (fp16)
__device__ __half   g_h16[(size_t)MAXN * 256];   // hidden activations (fp16)
__device__ __half   g_t16[(size_t)MAXN * 64];    // layer2 t (fp16, aggregated)
__device__ float    g_u[(size_t)MAXN * 64];      // layer2 u (fp32)
__device__ unsigned g_w1p[128 * 256];            // [W1l;W1r] row-concat, k-pair packed
__device__ unsigned g_w2p[128 * 128];            // [W2l|W2r] col-concat, k-pair packed

__device__ __forceinline__ unsigned packh2(float a, float b) {
    __half2 h = __floats2half2_rn(a, b);
    return *reinterpret_cast<unsigned*>(&h);
}

__device__ __forceinline__ __half2 u2h(unsigned u) {
    return *reinterpret_cast<__half2*>(&u);
}

__device__ __forceinline__ int off_final(int i) {
    return g_off[i] + g_bsum[i >> 10];
}

// ---------------- cp.async helpers ----------------
__device__ __forceinline__ void cp16(void* smem_dst, const void* gsrc, int srcbytes) {
    unsigned saddr = (unsigned)__cvta_generic_to_shared(smem_dst);
    asm volatile("cp.async.cg.shared.global [%0], [%1], 16, %2;"
                 :: "r"(saddr), "l"(gsrc), "r"(srcbytes));
}
#define CP_COMMIT() asm volatile("cp.async.commit_group;")
#define CP_WAIT0()  asm volatile("cp.async.wait_group 0;")
#define CP_WAIT1()  asm volatile("cp.async.wait_group 1;")

// ---------------- prep: x->fp16 | weight pack | dtype detect | edge count ----------------
__global__ void prep_kernel(const float* __restrict__ x,
                            const float* __restrict__ W1l, const float* __restrict__ W1r,
                            const float* __restrict__ W2l, const float* __restrict__ W2r,
                            const void* __restrict__ ei,
                            int N, int E, int convBlocks, int packBlocks) {
    int bx = blockIdx.x;
    if (bx < convBlocks) {
        int i = bx * 256 + threadIdx.x;
        int total4 = N * 32;
        if (i < total4) {
            float4 v = ((const float4*)x)[i];
            uint2 o;
            o.x = packh2(v.x, v.y);
            o.y = packh2(v.z, v.w);
            *(uint2*)&g_x16[(size_t)i * 4] = o;
        }
    } else if (bx < convBlocks + packBlocks) {
        int w = (bx - convBlocks) * 256 + threadIdx.x;
        if (w < 128 * 256) {
            int k2 = w >> 8, n = w & 255;
            int r0 = 2 * k2;
            float a, b;
            if (r0 < 128) {
                a = W1l[(size_t)r0 * 256 + n];
                b = W1l[(size_t)(r0 + 1) * 256 + n];
            } else {
                a = W1r[(size_t)(r0 - 128) * 256 + n];
                b = W1r[(size_t)(r0 - 127) * 256 + n];
            }
            g_w1p[w] = packh2(a, b);
        } else {
            int w2 = w - 128 * 256;
            if (w2 < 128 * 128) {
                int k2 = w2 >> 7, n = w2 & 127;
                int r0 = 2 * k2;
                float a, b;
                if (n < 64) {
                    a = W2l[(size_t)r0 * 64 + n];
                    b = W2l[(size_t)(r0 + 1) * 64 + n];
                } else {
                    a = W2r[(size_t)r0 * 64 + (n - 64)];
                    b = W2r[(size_t)(r0 + 1) * 64 + (n - 64)];
                }
                g_w2p[w2] = packh2(a, b);
            }
        }
    } else if (bx == convBlocks + packBlocks) {
        if (threadIdx.x < 32) {
            const int* eiw = (const int*)ei;
            int nz = (eiw[2 * threadIdx.x + 1] != 0);
            unsigned any = __ballot_sync(0xffffffffu, nz);
            if (threadIdx.x == 0) g_is64 = (any == 0) ? 1 : 0;
        }
    } else {
        __shared__ int s64;
        const int* eiw = (const int*)ei;
        if (threadIdx.x < 32) {
            int nz = (eiw[2 * threadIdx.x + 1] != 0);
            unsigned any = __ballot_sync(0xffffffffu, nz);
            if (threadIdx.x == 0) s64 = (any == 0) ? 1 : 0;
        }
        __syncthreads();
        int is64 = s64;
        int eb = bx - (convBlocks + packBlocks + 1);
        int base = (eb * 256 + threadIdx.x) * 4;
        if (base >= E) return;
        int d[4];
        bool full = (base + 3 < E);
        if (is64) {
            const long long* p = (const long long*)ei + E + base;
            if (full) {
                longlong2 a = *(const longlong2*)p;
                longlong2 b = *(const longlong2*)(p + 2);
                d[0] = (int)a.x; d[1] = (int)a.y; d[2] = (int)b.x; d[3] = (int)b.y;
            } else {
                #pragma unroll
                for (int j = 0; j < 4; j++) d[j] = (base + j < E) ? (int)p[j] : -1;
            }
        } else {
            const int* p = (const int*)ei + E + base;
            if (full) {
                int4 v = *(const int4*)p;
                d[0] = v.x; d[1] = v.y; d[2] = v.z; d[3] = v.w;
            } else {
                #pragma unroll
                for (int j = 0; j < 4; j++) d[j] = (base + j < E) ? p[j] : -1;
            }
        }
        #pragma unroll
        for (int j = 0; j < 4; j++)
            if ((unsigned)d[j] < (unsigned)N) atomicAdd(&g_deg[d[j]], 1);
    }
}

// ---------------- scan ----------------
__global__ void scan_blocks(int N, int B) {
    __shared__ int wsum[32];
    __shared__ int isLast;
    int i = blockIdx.x * 1024 + threadIdx.x;
    int lane = threadIdx.x & 31, wid = threadIdx.x >> 5;
    int v = (i < N) ? g_deg[i] : 0;
    int s = v;
    #pragma unroll
    for (int o = 1; o < 32; o <<= 1) {
        int t = __shfl_up_sync(0xffffffffu, s, o);
        if (lane >= o) s += t;
    }
    if (lane == 31) wsum[wid] = s;
    __syncthreads();
    if (wid == 0) {
        int ws = wsum[lane];
        #pragma unroll
        for (int o = 1; o < 32; o <<= 1) {
            int t = __shfl_up_sync(0xffffffffu, ws, o);
            if (lane >= o) ws += t;
        }
        wsum[lane] = ws;
    }
    __syncthreads();
    int incl = s + (wid > 0 ? wsum[wid - 1] : 0);
    if (i < N) {
        g_off[i] = incl - v;
        g_deg[i] = 0;
        g_cur[i] = 0;
    }
    if (threadIdx.x == 1023) g_bsum[blockIdx.x] = incl;
    __threadfence();
    __syncthreads();
    if (threadIdx.x == 0) {
        unsigned old = atomicAdd(&g_scan_ctr, 1);
        isLast = (old == (unsigned)(gridDim.x - 1)) ? 1 : 0;
    }
    __syncthreads();
    if (isLast) {
        if (threadIdx.x == 0) g_scan_ctr = 0;
        if (threadIdx.x < 32) {
            int carry = 0;
            for (int base = 0; base < B; base += 32) {
                int idx = base + lane;
                int v2 = (idx < B) ? g_bsum[idx] : 0;
                int s2 = v2;
                #pragma unroll
                for (int o = 1; o < 32; o <<= 1) {
                    int t = __shfl_up_sync(0xffffffffu, s2, o);
                    if (lane >= o) s2 += t;
                }
                if (idx < B) g_bsum[idx] = carry + s2 - v2;
                carry += __shfl_sync(0xffffffffu, s2, 31);
            }
        }
    }
}

// ---------------- fill (4 edges/thread) ----------------
__global__ void fill_kernel(const void* __restrict__ ei, int E, int N) {
    int base = (blockIdx.x * blockDim.x + threadIdx.x) * 4;
    if (base >= E) return;
    int s[4], d[4];
    bool full = (base + 3 < E);
    if (g_is64) {
        const long long* ps = (const long long*)ei + base;
        const long long* pd = (const long long*)ei + E + base;
        if (full) {
            longlong2 a = *(const longlong2*)ps, b = *(const longlong2*)(ps + 2);
            longlong2 c = *(const longlong2*)pd, e = *(const longlong2*)(pd + 2);
            s[0] = (int)a.x; s[1] = (int)a.y; s[2] = (int)b.x; s[3] = (int)b.y;
            d[0] = (int)c.x; d[1] = (int)c.y; d[2] = (int)e.x; d[3] = (int)e.y;
        } else {
            #pragma unroll
            for (int j = 0; j < 4; j++) {
                s[j] = (base + j < E) ? (int)ps[j] : -1;
                d[j] = (base + j < E) ? (int)pd[j] : -1;
            }
        }
    } else {
        const int* ps = (const int*)ei + base;
        const int* pd = (const int*)ei + E + base;
        if (full) {
            int4 a = *(const int4*)ps;
            int4 c = *(const int4*)pd;
            s[0] = a.x; s[1] = a.y; s[2] = a.z; s[3] = a.w;
            d[0] = c.x; d[1] = c.y; d[2] = c.z; d[3] = c.w;
        } else {
            #pragma unroll
            for (int j = 0; j < 4; j++) {
                s[j] = (base + j < E) ? ps[j] : -1;
                d[j] = (base + j < E) ? pd[j] : -1;
            }
        }
    }
    #pragma unroll
    for (int j = 0; j < 4; j++) {
        if ((unsigned)d[j] < (unsigned)N && (unsigned)s[j] < (unsigned)N) {
            int pos = off_final(d[j]) + atomicAdd(&g_cur[d[j]], 1);
            g_bucket[pos] = s[j];
        }
    }
}

// ---------------- layer-1 mean aggregation: 16 lanes/node, uint4 gathers (R15 form) ----------------
__global__ void agg128_kernel(int N, int E) {
    int lane = threadIdx.x & 15;                  // 16 lanes per node
    int node = blockIdx.x * 8 + (threadIdx.x >> 4);
    if (node >= N) return;
    int beg = off_final(node);
    int end = (node == N - 1) ? E : off_final(node + 1);
    unsigned lo = (unsigned)lane * 8;
    float acc[8];
    #pragma unroll
    for (int i = 0; i < 8; i++) acc[i] = 0.f;

    int e = beg;
    for (; e + 4 <= end; e += 4) {
        int s0 = g_bucket[e], s1 = g_bucket[e + 1], s2 = g_bucket[e + 2], s3 = g_bucket[e + 3];
        uint4 w0 = *(const uint4*)&g_x16[(size_t)((unsigned)s0 * 128u + lo)];
        uint4 w1 = *(const uint4*)&g_x16[(size_t)((unsigned)s1 * 128u + lo)];
        uint4 w2 = *(const uint4*)&g_x16[(size_t)((unsigned)s2 * 128u + lo)];
        uint4 w3 = *(const uint4*)&g_x16[(size_t)((unsigned)s3 * 128u + lo)];
        __half2 c0 = __hadd2(__hadd2(u2h(w0.x), u2h(w1.x)), __hadd2(u2h(w2.x), u2h(w3.x)));
        __half2 c1 = __hadd2(__hadd2(u2h(w0.y), u2h(w1.y)), __hadd2(u2h(w2.y), u2h(w3.y)));
        __half2 c2 = __hadd2(__hadd2(u2h(w0.z), u2h(w1.z)), __hadd2(u2h(w2.z), u2h(w3.z)));
        __half2 c3 = __hadd2(__hadd2(u2h(w0.w), u2h(w1.w)), __hadd2(u2h(w2.w), u2h(w3.w)));
        float2 f0 = __half22float2(c0), f1 = __half22float2(c1);
        float2 f2 = __half22float2(c2), f3 = __half22float2(c3);
        acc[0] += f0.x; acc[1] += f0.y; acc[2] += f1.x; acc[3] += f1.y;
        acc[4] += f2.x; acc[5] += f2.y; acc[6] += f3.x; acc[7] += f3.y;
    }
    for (; e < end; ++e) {
        int s = g_bucket[e];
        uint4 w = *(const uint4*)&g_x16[(size_t)((unsigned)s * 128u + lo)];
        float2 f0 = __half22float2(u2h(w.x)), f1 = __half22float2(u2h(w.y));
        float2 f2 = __half22float2(u2h(w.z)), f3 = __half22float2(u2h(w.w));
        acc[0] += f0.x; acc[1] += f0.y; acc[2] += f1.x; acc[3] += f1.y;
        acc[4] += f2.x; acc[5] += f2.y; acc[6] += f3.x; acc[7] += f3.y;
    }
    float inv = (end > beg) ? 1.f / (float)(end - beg) : 0.f;
    uint4 o;
    o.x = packh2(acc[0] * inv, acc[1] * inv);
    o.y = packh2(acc[2] * inv, acc[3] * inv);
    o.z = packh2(acc[4] * inv, acc[5] * inv);
    o.w = packh2(acc[6] * inv, acc[7] * inv);
    *(uint4*)&g_agg16[(size_t)((unsigned)node * 128u + lo)] = o;
}

// ---------------- fp16 MMA GEMMs (m16n8k16), 3-stage cp.async, single sync/iter ----------------
#define MMA_H16(d, a, b)                                                        \
    asm volatile(                                                               \
        "mma.sync.aligned.m16n8k16.row.col.f32.f16.f16.f32 "                    \
        "{%0,%1,%2,%3}, {%4,%5,%6,%7}, {%8,%9}, {%0,%1,%2,%3};"                 \
        : "+f"(d[0]), "+f"(d[1]), "+f"(d[2]), "+f"(d[3])                        \
        : "r"(a[0]), "r"(a[1]), "r"(a[2]), "r"(a[3]), "r"(b[0]), "r"(b[1]))

template <int MODE>
__global__ void __launch_bounds__(256, 2)
gemm_h16(const float* __restrict__ bias, int M) {
    __shared__ unsigned As[3][128][20];
    __shared__ unsigned Ws[3][16][136];

    const int NI = 8;
    const int WSTRIDE = (MODE == 0) ? 256 : 128;
    const unsigned* __restrict__ Wp = (MODE == 0) ? g_w1p : g_w2p;

    int tid = threadIdx.x;
    int lane = tid & 31;
    int wid = tid >> 5;
    int warp_m = wid & 1;
    int warp_n = wid >> 1;
    int qk = lane & 3;
    int qr = lane >> 2;
    int row0 = blockIdx.y * 128;
    int col0 = blockIdx.x * 128;

    int am = tid >> 2;
    int aq = tid & 3;
    int wk = tid >> 5;
    int wn = (tid & 31) * 4;

    float d[4][4][4];
    #pragma unroll
    for (int i = 0; i < 4; i++)
        #pragma unroll
        for (int j = 0; j < 4; j++)
            #pragma unroll
            for (int q = 0; q < 4; q++) d[i][j][q] = 0.f;

    auto issue = [&](int it) {
        int st = it % 3;
        int k0 = it * 32;
        #pragma unroll
        for (int j = 0; j < 2; j++) {
            int grow = row0 + am + j * 64;
            int gr = (grow < M) ? grow : 0;
            int sz = (grow < M) ? 16 : 0;
            const void* src;
            if (MODE == 0) {
                const __half* sp = (k0 < 128) ? g_agg16 : g_x16;
                src = &sp[(size_t)gr * 128 + (k0 & 127) + aq * 8];
            } else {
                src = &g_h16[(size_t)gr * 256 + k0 + aq * 8];
            }
            cp16(&As[st][am + j * 64][aq * 4], src, sz);
        }
        #pragma unroll
        for (int j = 0; j < 2; j++) {
            int k2 = it * 16 + wk + j * 8;
            cp16(&Ws[st][wk + j * 8][wn], &Wp[(size_t)k2 * WSTRIDE + col0 + wn], 16);
        }
        CP_COMMIT();
    };

    issue(0);
    issue(1);
    for (int it = 0; it < NI; ++it) {
        if (it + 1 < NI) CP_WAIT1(); else CP_WAIT0();
        __syncthreads();   // orders: all warps done MMA(it-1) AND stage(it) data visible
        if (it + 2 < NI) issue(it + 2);
        int st = it % 3;

        #pragma unroll
        for (int kk = 0; kk < 2; kk++) {
            int k2b = kk * 8;
            unsigned a[4][4], b[4][2];
            #pragma unroll
            for (int mf = 0; mf < 4; mf++) {
                int mrow = warp_m * 64 + mf * 16 + qr;
                a[mf][0] = As[st][mrow][k2b + qk];
                a[mf][1] = As[st][mrow + 8][k2b + qk];
                a[mf][2] = As[st][mrow][k2b + qk + 4];
                a[mf][3] = As[st][mrow + 8][k2b + qk + 4];
            }
            #pragma unroll
            for (int nf = 0; nf < 4; nf++) {
                int ncol = warp_n * 32 + nf * 8 + qr;
                b[nf][0] = Ws[st][k2b + qk][ncol];
                b[nf][1] = Ws[st][k2b + qk + 4][ncol];
            }
            #pragma unroll
            for (int mf = 0; mf < 4; mf++)
                #pragma unroll
                for (int nf = 0; nf < 4; nf++)
                    MMA_H16(d[mf][nf], a[mf], b[nf]);
        }
    }

    #pragma unroll
    for (int nf = 0; nf < 4; nf++) {
        int col = col0 + warp_n * 32 + nf * 8 + qk * 2;
        if (MODE == 0) {
            float2 bv = *(const float2*)&bias[col];
            #pragma unroll
            for (int mf = 0; mf < 4; mf++) {
                int r0 = row0 + warp_m * 64 + mf * 16 + qr;
                if (r0 < M) {
                    unsigned hh = packh2(fmaxf(d[mf][nf][0] + bv.x, 0.f),
                                         fmaxf(d[mf][nf][1] + bv.y, 0.f));
                    *(unsigned*)&g_h16[(size_t)r0 * 256 + col] = hh;
                }
                if (r0 + 8 < M) {
                    unsigned hh = packh2(fmaxf(d[mf][nf][2] + bv.x, 0.f),
                                         fmaxf(d[mf][nf][3] + bv.y, 0.f));
                    *(unsigned*)&g_h16[(size_t)(r0 + 8) * 256 + col] = hh;
                }
            }
        } else {
            #pragma unroll
            for (int mf = 0; mf < 4; mf++) {
                int r0 = row0 + warp_m * 64 + mf * 16 + qr;
                if (col < 64) {
                    if (r0 < M) {
                        unsigned hh = packh2(d[mf][nf][0], d[mf][nf][1]);
                        *(unsigned*)&g_t16[(size_t)r0 * 64 + col] = hh;
                    }
                    if (r0 + 8 < M) {
                        unsigned hh = packh2(d[mf][nf][2], d[mf][nf][3]);
                        *(unsigned*)&g_t16[(size_t)(r0 + 8) * 64 + col] = hh;
                    }
                } else {
                    if (r0 < M) {
                        float2 o = make_float2(d[mf][nf][0], d[mf][nf][1]);
                        *(float2*)&g_u[(size_t)r0 * 64 + (col - 64)] = o;
                    }
                    if (r0 + 8 < M) {
                        float2 o = make_float2(d[mf][nf][2], d[mf][nf][3]);
                        *(float2*)&g_u[(size_t)(r0 + 8) * 64 + (col - 64)] = o;
                    }
                }
            }
        }
    }
}

// ---------------- final: 8 lanes/node, uint4 gathers (R15 form) ----------------
__global__ void agg_sig_kernel(const float* __restrict__ b2, float* __restrict__ out,
                               int N, int E) {
    int lane = threadIdx.x & 7;                   // 8 lanes per node
    int node = blockIdx.x * 16 + (threadIdx.x >> 3);
    if (node >= N) return;
    int beg = off_final(node);
    int end = (node == N - 1) ? E : off_final(node + 1);
    unsigned lo = (unsigned)lane * 8;
    float acc[8];
    #pragma unroll
    for (int i = 0; i < 8; i++) acc[i] = 0.f;

    int e = beg;
    for (; e + 4 <= end; e += 4) {
        int s0 = g_bucket[e], s1 = g_bucket[e + 1], s2 = g_bucket[e + 2], s3 = g_bucket[e + 3];
        uint4 w0 = *(const uint4*)&g_t16[(size_t)((unsigned)s0 * 64u + lo)];
        uint4 w1 = *(const uint4*)&g_t16[(size_t)((unsigned)s1 * 64u + lo)];
        uint4 w2 = *(const uint4*)&g_t16[(size_t)((unsigned)s2 * 64u + lo)];
        uint4 w3 = *(const uint4*)&g_t16[(size_t)((unsigned)s3 * 64u + lo)];
        __half2 c0 = __hadd2(__hadd2(u2h(w0.x), u2h(w1.x)), __hadd2(u2h(w2.x), u2h(w3.x)));
        __half2 c1 = __hadd2(__hadd2(u2h(w0.y), u2h(w1.y)), __hadd2(u2h(w2.y), u2h(w3.y)));
        __half2 c2 = __hadd2(__hadd2(u2h(w0.z), u2h(w1.z)), __hadd2(u2h(w2.z), u2h(w3.z)));
        __half2 c3 = __hadd2(__hadd2(u2h(w0.w), u2h(w1.w)), __hadd2(u2h(w2.w), u2h(w3.w)));
        float2 f0 = __half22float2(c0), f1 = __half22float2(c1);
        float2 f2 = __half22float2(c2), f3 = __half22float2(c3);
        acc[0] += f0.x; acc[1] += f0.y; acc[2] += f1.x; acc[3] += f1.y;
        acc[4] += f2.x; acc[5] += f2.y; acc[6] += f3.x; acc[7] += f3.y;
    }
    for (; e < end; ++e) {
        int s = g_bucket[e];
        uint4 w = *(const uint4*)&g_t16[(size_t)((unsigned)s * 64u + lo)];
        float2 f0 = __half22float2(u2h(w.x)), f1 = __half22float2(u2h(w.y));
        float2 f2 = __half22float2(u2h(w.z)), f3 = __half22float2(u2h(w.w));
        acc[0] += f0.x; acc[1] += f0.y; acc[2] += f1.x; acc[3] += f1.y;
        acc[4] += f2.x; acc[5] += f2.y; acc[6] += f3.x; acc[7] += f3.y;
    }
    float inv = (end > beg) ? 1.f / (float)(end - beg) : 0.f;
    float4 u0 = *(const float4*)&g_u[(size_t)((unsigned)node * 64u + lo)];
    float4 u1 = *(const float4*)&g_u[(size_t)((unsigned)node * 64u + lo + 4)];
    float4 b0 = *(const float4*)&b2[lo];
    float4 b1 = *(const float4*)&b2[lo + 4];
    float4 o0, o1;
    o0.x = 1.f / (1.f + __expf(-(acc[0] * inv + u0.x + b0.x)));
    o0.y = 1.f / (1.f + __expf(-(acc[1] * inv + u0.y + b0.y)));
    o0.z = 1.f / (1.f + __expf(-(acc[2] * inv + u0.z + b0.z)));
    o0.w = 1.f / (1.f + __expf(-(acc[3] * inv + u0.w + b0.w)));
    o1.x = 1.f / (1.f + __expf(-(acc[4] * inv + u1.x + b1.x)));
    o1.y = 1.f / (1.f + __expf(-(acc[5] * inv + u1.y + b1.y)));
    o1.z = 1.f / (1.f + __expf(-(acc[6] * inv + u1.z + b1.z)));
    o1.w = 1.f / (1.f + __expf(-(acc[7] * inv + u1.w + b1.w)));
    float* op = &out[(size_t)((unsigned)node * 64u + lo)];
    *(float4*)op = o0;
    *(float4*)(op + 4) = o1;
}

// ---------------- launch ----------------
extern "C" void kernel_launch(void* const* d_in, const int* in_sizes, int n_in,
                              void* d_out, int out_size) {
    const float* x   = (const float*)d_in[0];
    const void*  ei  = d_in[1];
    const float* W1l = (const float*)d_in[2];
    const float* W1r = (const float*)d_in[3];
    const float* b1  = (const float*)d_in[4];
    const float* W2l = (const float*)d_in[5];
    const float* W2r = (const float*)d_in[6];
    const float* b2  = (const float*)d_in[7];
    float* out = (float*)d_out;

    int N = in_sizes[0] / 128;
    int E = in_sizes[1] / 2;
    int B = (N + 1023) / 1024;

    int convBlocks = (N * 32 + 255) / 256;
    int packBlocks = (128 * 256 + 128 * 128 + 255) / 256;
    int E4blocks = ((E + 3) / 4 + 255) / 256;

    prep_kernel<<<convBlocks + packBlocks + 1 + E4blocks, 256>>>(
        x, W1l, W1r, W2l, W2r, ei, N, E, convBlocks, packBlocks);
    scan_blocks<<<B, 1024>>>(N, B);
    fill_kernel<<<E4blocks, 256>>>(ei, E, N);
    agg128_kernel<<<(N + 7) / 8, 128>>>(N, E);
    {
        dim3 grid(2, (N + 127) / 128);
        gemm_h16<0><<<grid, 256>>>(b1, N);
    }
    {
        dim3 grid(1, (N + 127) / 128);
        gemm_h16<1><<<grid, 256>>>(nullptr, N);
    }
    agg_sig_kernel<<<(N + 15) / 16, 128>>>(b2, out, N, E);
}